// round 11
// baseline (speedup 1.0000x reference)
#include <cuda_runtime.h>
#include <cuda_bf16.h>
#include <cstdint>
#include <math.h>

#define B 8
#define S 2048
#define D 2048
#define E 8
#define EPS 1e-5f

#define D4 (D / 4)            // 512 float4 per row
#define S_CHUNK 32            // rows per CTA
#define GY (S / S_CHUNK)      // 64
#define NBLK (GY * B)         // 512
#define NS 4                  // pipeline stages (1 row = 8KB each)

__device__ float g_acc[B * E + B];
__device__ unsigned int g_ticket;

__device__ __forceinline__ uint32_t smem_u32(const void* p) {
    uint32_t a;
    asm("{ .reg .u64 t; cvta.to.shared.u64 t, %1; cvt.u32.u64 %0, t; }"
        : "=r"(a) : "l"(p));
    return a;
}
__device__ __forceinline__ void cp16(uint32_t saddr, const void* gptr) {
    asm volatile("cp.async.cg.shared.global [%0], [%1], 16;"
                 :: "r"(saddr), "l"(gptr) : "memory");
}
__device__ __forceinline__ void cp_commit() {
    asm volatile("cp.async.commit_group;" ::: "memory");
}
__device__ __forceinline__ void cp_wait() {
    asm volatile("cp.async.wait_group %0;" :: "n"(NS - 2) : "memory");
}

__global__ void __launch_bounds__(256) router_kernel(
    const float*  __restrict__ x,
    const float4* __restrict__ W4,
    const float*  __restrict__ gain,
    const float*  __restrict__ init_std,
    const float*  __restrict__ noise,
    const int*    __restrict__ topk_p,
    float* __restrict__ out, int out_size)
{
    extern __shared__ __align__(16) float4 sb[];   // NS * 512 float4 = 32 KB
    __shared__ float s_red[9][8];

    const int tid  = threadIdx.x;                  // 0..255
    const int warp = tid >> 5, lane = tid & 31;
    const int b    = blockIdx.y;
    const int s0   = blockIdx.x * S_CHUNK;

    const float* src = x + ((size_t)b * S + s0) * D;
    const uint32_t sbase = smem_u32(sb);

    // prologue: stages 0..NS-2
#pragma unroll
    for (int s = 0; s < NS - 1; s++) {
        uint32_t dst = sbase + (uint32_t)s * 8192;
        const float* g = src + (size_t)s * D;
        cp16(dst + tid * 16,          g + tid * 4);
        cp16(dst + (tid + 256) * 16,  g + (tid + 256) * 4);
        cp_commit();
    }

    float4 acc0 = make_float4(0.f, 0.f, 0.f, 0.f);   // column d4 = tid
    float4 acc1 = make_float4(0.f, 0.f, 0.f, 0.f);   // column d4 = tid+256
    for (int c = 0; c < S_CHUNK; c++) {
        // issue stage c+NS-1 (always commit so wait_group stays positional)
        const int pre = c + NS - 1;
        if (pre < S_CHUNK) {
            uint32_t dst = sbase + (uint32_t)(pre % NS) * 8192;
            const float* g = src + (size_t)pre * D;
            cp16(dst + tid * 16,         g + tid * 4);
            cp16(dst + (tid + 256) * 16, g + (tid + 256) * 4);
        }
        cp_commit();

        cp_wait();                                   // stage c complete (mine)
        __syncthreads();                             // complete for all threads

        const float4* bb = sb + (c % NS) * 512;
        float4 a0 = bb[tid];
        float4 a1 = bb[tid + 256];
        acc0.x += a0.x; acc0.y += a0.y; acc0.z += a0.z; acc0.w += a0.w;
        acc1.x += a1.x; acc1.y += a1.y; acc1.z += a1.z; acc1.w += a1.w;

        __syncthreads();                             // stage slot reusable
    }

    // ---- contract against W in-registers: 9 partials per thread ----
    float v9[9];
#pragma unroll
    for (int e = 0; e < E; e++) {
        float4 w0 = W4[e * D4 + tid];
        float4 w1 = W4[e * D4 + tid + 256];
        v9[e] = acc0.x * w0.x + acc0.y * w0.y + acc0.z * w0.z + acc0.w * w0.w
              + acc1.x * w1.x + acc1.y * w1.y + acc1.z * w1.z + acc1.w * w1.w;
    }
    v9[8] = acc0.x + acc0.y + acc0.z + acc0.w
          + acc1.x + acc1.y + acc1.z + acc1.w;

    // ---- block reduce 9 values ----
#pragma unroll
    for (int o = 16; o; o >>= 1)
#pragma unroll
        for (int i = 0; i < 9; i++)
            v9[i] += __shfl_xor_sync(0xFFFFFFFFu, v9[i], o);
    if (lane == 0)
#pragma unroll
        for (int i = 0; i < 9; i++) s_red[i][warp] = v9[i];
    __syncthreads();
    if (tid < 9) {
        float s = 0.f;
#pragma unroll
        for (int w = 0; w < 8; w++) s += s_red[tid][w];
        atomicAdd(&g_acc[tid < 8 ? b * E + tid : 64 + b], s);
    }

    // ---- last-block ticket ----
    __syncthreads();
    __shared__ bool is_last;
    if (tid == 0) {
        __threadfence();
        unsigned t = atomicAdd(&g_ticket, 1u);
        is_last = (t == NBLK - 1);
    }
    __syncthreads();
    if (!is_last) return;

    // ================= finalize (one block) =================
    __shared__ float s_dot[B * E], s_xsum[B], s_scale[E], s_mean[E];
    if (tid < B * E) s_dot[tid] = __ldcg(&g_acc[tid]);
    if (tid < B)     s_xsum[tid] = __ldcg(&g_acc[64 + tid]);

    {   // per-expert W stats: warp e -> expert e (L2-hot)
        const float4* wrow = W4 + warp * D4;
        float s = 0.f, ss = 0.f;
#pragma unroll 4
        for (int i = lane; i < D4; i += 32) {
            float4 w = wrow[i];
            s  += w.x + w.y + w.z + w.w;
            ss += w.x * w.x + w.y * w.y + w.z * w.z + w.w * w.w;
        }
#pragma unroll
        for (int o = 16; o; o >>= 1) {
            s  += __shfl_xor_sync(0xFFFFFFFFu, s,  o);
            ss += __shfl_xor_sync(0xFFFFFFFFu, ss, o);
        }
        if (lane == 0) {
            float mean = s / (float)D;
            float var  = (ss - (float)D * mean * mean) / (float)(D - 1);
            float std  = sqrtf(fmaxf(var, 0.f)) + EPS;
            s_mean[warp]  = mean;
            s_scale[warp] = init_std[warp] / std * gain[warp];
        }
    }
    __syncthreads();

    if (tid < B) {
        const int bb = tid;
        int k = *topk_p;
        if (k > E) k = E;
        const float invS = 1.0f / (float)S;
        float sc[E];
        float mx = -INFINITY;
#pragma unroll
        for (int e = 0; e < E; e++) {
            float v = s_scale[e] * (s_dot[bb * E + e] - s_mean[e] * s_xsum[bb]) * invS
                      + noise[bb * E + e];
            sc[e] = v;
            mx = fmaxf(mx, v);
        }
        float denom = 0.f;
#pragma unroll
        for (int e = 0; e < E; e++) { sc[e] = expf(sc[e] - mx); denom += sc[e]; }
        float inv = 1.0f / denom;
#pragma unroll
        for (int e = 0; e < E; e++) sc[e] *= inv;

        float comb[E];
        bool taken[E];
#pragma unroll
        for (int e = 0; e < E; e++) { comb[e] = 0.f; taken[e] = false; }

        for (int kk = 0; kk < k; kk++) {
            int best = -1; float bv = -INFINITY;
            for (int e = 0; e < E; e++)
                if (!taken[e] && sc[e] > bv) { bv = sc[e]; best = e; }
            taken[best] = true;
            comb[best] = bv;
            int idx_off = B * E + bb * k + kk;
            int scr_off = B * E + B * k + bb * k + kk;
            if (idx_off < out_size) out[idx_off] = (float)best;
            if (scr_off < out_size) out[scr_off] = bv;
        }
#pragma unroll
        for (int e = 0; e < E; e++) {
            int o = bb * E + e;
            if (o < out_size) out[o] = comb[e];
        }
    }
    __syncthreads();

    // reset scratch for next graph replay
    if (tid < B * E + B) g_acc[tid] = 0.f;
    if (tid == 0) g_ticket = 0u;
}

extern "C" void kernel_launch(void* const* d_in, const int* in_sizes, int n_in,
                              void* d_out, int out_size) {
    const float* x        = (const float*)d_in[0];
    const float* W        = (const float*)d_in[1];
    const float* gain     = (const float*)d_in[2];
    const float* init_std = (const float*)d_in[3];
    const float* noise    = (const float*)d_in[4];
    const int*   topk     = (const int*)d_in[5];
    float* out = (float*)d_out;

    dim3 grid(GY, B);
    router_kernel<<<grid, 256, NS * 8192>>>(
        x, (const float4*)W, gain, init_std, noise, topk, out, out_size);
}

// round 12
// speedup vs baseline: 1.1570x; 1.1570x over previous
#include <cuda_runtime.h>
#include <cuda_bf16.h>
#include <math.h>

#define B 8
#define S 2048
#define D 2048
#define E 8
#define EPS 1e-5f

#define D4 (D / 4)            // 512 float4 per row
#define S_CHUNK 64            // rows per CTA (R2 best)
#define GX 2                  // D4 / 256
#define GY (S / S_CHUNK)      // 32
#define NBLK (GX * GY * B)    // 512

// Scratch, zero-init; finalizing block re-zeroes for graph replay.
__device__ float g_acc[B * E + B];
__device__ float g_stats[2 * E];         // [mean, scale] per expert
__device__ unsigned int g_ticket;

__global__ void __launch_bounds__(256) router_kernel(
    const float4* __restrict__ x4,
    const float4* __restrict__ W4,
    const float*  __restrict__ gain,
    const float*  __restrict__ init_std,
    const float*  __restrict__ noise,
    const int*    __restrict__ topk_p,
    float* __restrict__ out, int out_size)
{
    const int tid  = threadIdx.x;
    const int warp = tid >> 5, lane = tid & 31;
    const int d4   = blockIdx.x * 256 + tid;      // 0..511
    const int b    = blockIdx.z;
    const int s0   = blockIdx.y * S_CHUNK;
    const int bid  = (blockIdx.z * GY + blockIdx.y) * GX + blockIdx.x;

    // ---- stream x: partial column sums over S_CHUNK rows (R2 config) ----
    const float4* p = x4 + ((size_t)b * S + s0) * D4 + d4;
    float4 acc = make_float4(0.f, 0.f, 0.f, 0.f);
#pragma unroll 8
    for (int i = 0; i < S_CHUNK; i++) {
        float4 v = p[(size_t)i * D4];
        acc.x += v.x; acc.y += v.y; acc.z += v.z; acc.w += v.w;
    }

    // ---- contract against W in-registers: 9 partials per thread ----
    float v9[9];
#pragma unroll
    for (int e = 0; e < E; e++) {
        float4 w = W4[e * D4 + d4];
        v9[e] = acc.x * w.x + acc.y * w.y + acc.z * w.z + acc.w * w.w;
    }
    v9[8] = acc.x + acc.y + acc.z + acc.w;        // xsum partial

    // ---- block reduce 9 values ----
    __shared__ float s_red[9][8];
#pragma unroll
    for (int o = 16; o; o >>= 1)
#pragma unroll
        for (int i = 0; i < 9; i++)
            v9[i] += __shfl_xor_sync(0xFFFFFFFFu, v9[i], o);
    if (lane == 0)
#pragma unroll
        for (int i = 0; i < 9; i++) s_red[i][warp] = v9[i];
    __syncthreads();
    if (tid < 9) {
        float s = 0.f;
#pragma unroll
        for (int w = 0; w < 8; w++) s += s_red[tid][w];
        atomicAdd(&g_acc[tid < 8 ? b * E + tid : 64 + b], s);
    }

    // ---- CTAs 0..7: per-expert W stats, overlapped with other CTAs' streams ----
    if (bid < E) {
        const int e = bid;
        const float4* wrow = W4 + e * D4;
        float s = 0.f, ss = 0.f;
#pragma unroll
        for (int i = 0; i < 2; i++) {
            float4 w = wrow[tid * 2 + i];          // 256 thr x 2 float4 = full row
            s  += w.x + w.y + w.z + w.w;
            ss += w.x * w.x + w.y * w.y + w.z * w.z + w.w * w.w;
        }
#pragma unroll
        for (int o = 16; o; o >>= 1) {
            s  += __shfl_xor_sync(0xFFFFFFFFu, s,  o);
            ss += __shfl_xor_sync(0xFFFFFFFFu, ss, o);
        }
        __shared__ float s_s[8], s_ss[8];
        if (lane == 0) { s_s[warp] = s; s_ss[warp] = ss; }
        __syncthreads();
        if (tid == 0) {
            float ts = 0.f, tss = 0.f;
#pragma unroll
            for (int w = 0; w < 8; w++) { ts += s_s[w]; tss += s_ss[w]; }
            float mean = ts / (float)D;
            float var  = (tss - (float)D * mean * mean) / (float)(D - 1);
            float std  = sqrtf(fmaxf(var, 0.f)) + EPS;
            g_stats[2 * e]     = mean;
            g_stats[2 * e + 1] = init_std[e] / std * gain[e];
        }
    }

    // ---- last-block ticket: one fence + one atomic per CTA ----
    __syncthreads();
    __shared__ bool is_last;
    if (tid == 0) {
        __threadfence();
        unsigned t = atomicAdd(&g_ticket, 1u);
        is_last = (t == NBLK - 1);
    }
    __syncthreads();
    if (!is_last) return;

    // ================= finalize (tiny, fully overlapped W stats) =================
    __shared__ float s_dot[B * E], s_xsum[B], s_scale[E], s_mean[E];
    if (tid < B * E) s_dot[tid]  = __ldcg(&g_acc[tid]);
    if (tid < B)     s_xsum[tid] = __ldcg(&g_acc[64 + tid]);
    if (tid < E) {
        s_mean[tid]  = __ldcg(&g_stats[2 * tid]);
        s_scale[tid] = __ldcg(&g_stats[2 * tid + 1]);
    }
    __syncthreads();

    if (tid < B) {
        const int bb = tid;
        int k = *topk_p;
        if (k > E) k = E;
        const float invS = 1.0f / (float)S;
        float sc[E];
        float mx = -INFINITY;
#pragma unroll
        for (int e = 0; e < E; e++) {
            float v = s_scale[e] * (s_dot[bb * E + e] - s_mean[e] * s_xsum[bb]) * invS
                      + noise[bb * E + e];
            sc[e] = v;
            mx = fmaxf(mx, v);
        }
        float denom = 0.f;
#pragma unroll
        for (int e = 0; e < E; e++) { sc[e] = expf(sc[e] - mx); denom += sc[e]; }
        float inv = 1.0f / denom;
#pragma unroll
        for (int e = 0; e < E; e++) sc[e] *= inv;

        float comb[E];
        bool taken[E];
#pragma unroll
        for (int e = 0; e < E; e++) { comb[e] = 0.f; taken[e] = false; }

        for (int kk = 0; kk < k; kk++) {
            int best = -1; float bv = -INFINITY;
            for (int e = 0; e < E; e++)
                if (!taken[e] && sc[e] > bv) { bv = sc[e]; best = e; }
            taken[best] = true;
            comb[best] = bv;
            int idx_off = B * E + bb * k + kk;
            int scr_off = B * E + B * k + bb * k + kk;
            if (idx_off < out_size) out[idx_off] = (float)best;
            if (scr_off < out_size) out[scr_off] = bv;
        }
#pragma unroll
        for (int e = 0; e < E; e++) {
            int o = bb * E + e;
            if (o < out_size) out[o] = comb[e];
        }
    }
    __syncthreads();

    // reset scratch for next graph replay
    if (tid < B * E + B) g_acc[tid] = 0.f;
    if (tid == 0) g_ticket = 0u;
}

extern "C" void kernel_launch(void* const* d_in, const int* in_sizes, int n_in,
                              void* d_out, int out_size) {
    const float* x        = (const float*)d_in[0];
    const float* W        = (const float*)d_in[1];
    const float* gain     = (const float*)d_in[2];
    const float* init_std = (const float*)d_in[3];
    const float* noise    = (const float*)d_in[4];
    const int*   topk     = (const int*)d_in[5];
    float* out = (float*)d_out;

    dim3 grid(GX, GY, B);
    router_kernel<<<grid, 256>>>((const float4*)x, (const float4*)W,
                                 gain, init_std, noise, topk, out, out_size);
}